// round 1
// baseline (speedup 1.0000x reference)
#include <cuda_runtime.h>

#define NPTS  32768
#define P     16
#define NC    8192
#define E     (NC * P)
#define IN_F  64
#define OUT_F 128
#define TM    32

// Scratch: per-(center, kernel-point) summed influence coefficient.
// coef[c,k] = sum over neighbors n of center c with argmin kernel == k of w(c,n)
__device__ float g_coef[E];

// ---------------------------------------------------------------------------
// Pass 1: geometry. One thread per edge. Edges are grouped 16-per-center, so a
// 16-lane shuffle group reduces the (argmin, weight) pairs into coef[c, 0..15]
// with no atomics and no scratch zeroing.
// ---------------------------------------------------------------------------
__global__ void __launch_bounds__(256) kp_geom_kernel(
    const float* __restrict__ pos,
    const int*   __restrict__ edge_src,
    const int*   __restrict__ edge_tgt,
    const float* __restrict__ kpts)
{
    int e    = blockIdx.x * 256 + threadIdx.x;
    int lane = threadIdx.x & 31;

    int ti = edge_tgt[e];
    int si = edge_src[e];
    float rx = pos[ti * 3 + 0] - pos[si * 3 + 0];
    float ry = pos[ti * 3 + 1] - pos[si * 3 + 1];
    float rz = pos[ti * 3 + 2] - pos[si * 3 + 2];

    float best = 3.402823466e38f;
    int   nn   = 0;
#pragma unroll
    for (int k = 0; k < P; ++k) {
        float dx = rx - kpts[k * 3 + 0];
        float dy = ry - kpts[k * 3 + 1];
        float dz = rz - kpts[k * 3 + 2];
        float d2 = dx * dx + dy * dy + dz * dz;
        if (d2 < best) { best = d2; nn = k; }   // strict < keeps first min (jnp.argmin)
    }
    // KP_EXTENT = 1/1.5 -> 1/KP_EXTENT = 1.5
    float w = fmaxf(1.0f - sqrtf(best) * 1.5f, 0.0f);

    // Reduce within the 16-lane group (one center). Lane's sub-index is the
    // kernel point it accumulates the coefficient for.
    int   half = lane & 16;
    int   myk  = lane & 15;
    float coef = 0.0f;
#pragma unroll
    for (int j = 0; j < 16; ++j) {
        int   nnj = __shfl_sync(0xffffffffu, nn, half + j);
        float wj  = __shfl_sync(0xffffffffu, w,  half + j);
        if (nnj == myk) coef += wj;
    }
    // e = c*16 + myk for this lane
    g_coef[e] = coef;
}

// ---------------------------------------------------------------------------
// Pass 2: main compute. One CTA per TM=32 centers. For each kernel point k:
//   stage W[k] (64x128 fp32 = 32KB) in smem, gather+scale 32 feature rows into
//   smem, then accumulate the [32,128] output tile with 4x4 register tiles.
// ---------------------------------------------------------------------------
__global__ void __launch_bounds__(256) kp_main_kernel(
    const float* __restrict__ x,
    const int*   __restrict__ edge_src,
    const float* __restrict__ kw,
    float*       __restrict__ out)
{
    __shared__ float Ws[IN_F * OUT_F];        // 32 KB, W[k] row-major [i][o]
    __shared__ float As[TM][IN_F + 4];        // padded gathered+scaled rows

    const int tid = threadIdx.x;
    const int c0  = blockIdx.x * TM;
    const int cg  = tid >> 5;                 // 0..7  -> centers 4*cg .. 4*cg+3
    const int og  = tid & 31;                 // 0..31 -> out cols 4*og .. 4*og+3

    float acc[4][4];
#pragma unroll
    for (int r = 0; r < 4; ++r)
#pragma unroll
        for (int s = 0; s < 4; ++s) acc[r][s] = 0.0f;

    const int row  = tid >> 3;                // 0..31 : which A row this thread fills
    const int part = tid & 7;                 // 8 threads per row, 8 floats each

    for (int k = 0; k < P; ++k) {
        __syncthreads();

        // Stage W[k]: 8192 floats = 2048 float4, 8 per thread, coalesced.
        const float4* Wk = (const float4*)(kw + (size_t)k * IN_F * OUT_F);
        float4*       Wv = (float4*)Ws;
#pragma unroll
        for (int j = 0; j < 8; ++j) Wv[tid + 256 * j] = Wk[tid + 256 * j];

        // Gather + scale A rows: row 'row' uses edge (c0+row)*16 + k.
        {
            int   eidx = (c0 + row) * P + k;
            int   src  = edge_src[eidx];
            float coef = g_coef[eidx];
            const float4* xr = (const float4*)(x + (size_t)src * IN_F);
            float4 v0 = xr[part * 2 + 0];
            float4 v1 = xr[part * 2 + 1];
            float* dst = &As[row][part * 8];
            dst[0] = v0.x * coef; dst[1] = v0.y * coef;
            dst[2] = v0.z * coef; dst[3] = v0.w * coef;
            dst[4] = v1.x * coef; dst[5] = v1.y * coef;
            dst[6] = v1.z * coef; dst[7] = v1.w * coef;
        }
        __syncthreads();

        // MAC: acc[r][s] += A[4cg+r][i] * W[i][4og+s]
#pragma unroll
        for (int i = 0; i < IN_F; ++i) {
            float4 w4 = ((const float4*)(Ws + i * OUT_F))[og];
            float a0 = As[cg * 4 + 0][i];
            float a1 = As[cg * 4 + 1][i];
            float a2 = As[cg * 4 + 2][i];
            float a3 = As[cg * 4 + 3][i];
            acc[0][0] += a0 * w4.x; acc[0][1] += a0 * w4.y;
            acc[0][2] += a0 * w4.z; acc[0][3] += a0 * w4.w;
            acc[1][0] += a1 * w4.x; acc[1][1] += a1 * w4.y;
            acc[1][2] += a1 * w4.z; acc[1][3] += a1 * w4.w;
            acc[2][0] += a2 * w4.x; acc[2][1] += a2 * w4.y;
            acc[2][2] += a2 * w4.z; acc[2][3] += a2 * w4.w;
            acc[3][0] += a3 * w4.x; acc[3][1] += a3 * w4.y;
            acc[3][2] += a3 * w4.z; acc[3][3] += a3 * w4.w;
        }
    }

    // Write the [32,128] tile. Fully overwrites the (poisoned) output.
#pragma unroll
    for (int r = 0; r < 4; ++r) {
        int c = c0 + cg * 4 + r;
        float4 o4 = make_float4(acc[r][0], acc[r][1], acc[r][2], acc[r][3]);
        ((float4*)(out + (size_t)c * OUT_F))[og] = o4;
    }
}

extern "C" void kernel_launch(void* const* d_in, const int* in_sizes, int n_in,
                              void* d_out, int out_size)
{
    const float* x        = (const float*)d_in[0];
    const float* pos      = (const float*)d_in[1];
    const int*   edge_src = (const int*)  d_in[2];
    const int*   edge_tgt = (const int*)  d_in[3];
    const float* kpts     = (const float*)d_in[4];
    const float* kw       = (const float*)d_in[5];
    float*       out      = (float*)d_out;

    kp_geom_kernel<<<E / 256, 256>>>(pos, edge_src, edge_tgt, kpts);
    kp_main_kernel<<<NC / TM, 256>>>(x, edge_src, kw, out);
}

// round 2
// speedup vs baseline: 1.0584x; 1.0584x over previous
#include <cuda_runtime.h>

#define NPTS  32768
#define P     16
#define NC    8192
#define E     (NC * P)
#define IN_F  64
#define OUT_F 128
#define TM    32                 // centers per CTA
#define AS_S  36                 // As_t row stride (floats), mult of 4 for LDS.128

// Scratch: per-(center, kernel-point) summed influence coefficient.
__device__ float g_coef[E];

// ---------------------------------------------------------------------------
// Pass 1: geometry. One thread per edge; 16-lane shuffle-group reduction of
// (argmin kernel idx, clamped linear influence) into coef[c, 0..15].
// ---------------------------------------------------------------------------
__global__ void __launch_bounds__(256) kp_geom_kernel(
    const float* __restrict__ pos,
    const int*   __restrict__ edge_src,
    const int*   __restrict__ edge_tgt,
    const float* __restrict__ kpts)
{
    int e    = blockIdx.x * 256 + threadIdx.x;
    int lane = threadIdx.x & 31;

    int ti = edge_tgt[e];
    int si = edge_src[e];
    float rx = pos[ti * 3 + 0] - pos[si * 3 + 0];
    float ry = pos[ti * 3 + 1] - pos[si * 3 + 1];
    float rz = pos[ti * 3 + 2] - pos[si * 3 + 2];

    float best = 3.402823466e38f;
    int   nn   = 0;
#pragma unroll
    for (int k = 0; k < P; ++k) {
        float dx = rx - kpts[k * 3 + 0];
        float dy = ry - kpts[k * 3 + 1];
        float dz = rz - kpts[k * 3 + 2];
        float d2 = dx * dx + dy * dy + dz * dz;
        if (d2 < best) { best = d2; nn = k; }   // strict < == jnp.argmin first-min
    }
    float w = fmaxf(1.0f - sqrtf(best) * 1.5f, 0.0f);   // 1/KP_EXTENT = 1.5

    int   half = lane & 16;
    int   myk  = lane & 15;
    float coef = 0.0f;
#pragma unroll
    for (int j = 0; j < 16; ++j) {
        int   nnj = __shfl_sync(0xffffffffu, nn, half + j);
        float wj  = __shfl_sync(0xffffffffu, w,  half + j);
        if (nnj == myk) coef += wj;
    }
    g_coef[e] = coef;
}

// ---------------------------------------------------------------------------
// f32x2 helpers
// ---------------------------------------------------------------------------
__device__ __forceinline__ void ffma2(unsigned long long& d,
                                      unsigned long long a,
                                      unsigned long long b)
{
    asm("fma.rn.f32x2 %0, %1, %2, %0;" : "+l"(d) : "l"(a), "l"(b));
}
__device__ __forceinline__ unsigned long long splat2(float a)
{
    unsigned long long r;
    asm("mov.b64 %0, {%1, %1};" : "=l"(r) : "f"(a));
    return r;
}

// ---------------------------------------------------------------------------
// Pass 2: main compute. One CTA per 32 centers, 128 threads.
// Per kernel point k: stage W[k] (64x128, 32KB) in smem, gather+scale 32
// feature rows TRANSPOSED into As_t[i][row], then accumulate [32,128] with
// 4x8 register tiles using packed fma.rn.f32x2.
// ---------------------------------------------------------------------------
__global__ void __launch_bounds__(128) kp_main_kernel(
    const float* __restrict__ x,
    const int*   __restrict__ edge_src,
    const float* __restrict__ kw,
    float*       __restrict__ out)
{
    __shared__ float Ws[IN_F * OUT_F];        // 32 KB, W[k] row-major [i][o]
    __shared__ float As_t[IN_F * AS_S];       // transposed A: As_t[i*AS_S + row]

    const int tid = threadIdx.x;
    const int c0  = blockIdx.x * TM;

    // MAC mapping: cx in [0,16) -> cols {cx*4..cx*4+3, 64+cx*4..64+cx*4+3}
    //              rt in [0,8)  -> rows rt*4..rt*4+3
    const int cx = tid & 15;
    const int rt = tid >> 4;

    // Fill mapping: frow in [0,32) row, fpart in [0,4) which 16-i chunk
    const int frow  = tid >> 2;
    const int fpart = tid & 3;

    unsigned long long acc[4][4];
#pragma unroll
    for (int r = 0; r < 4; ++r)
#pragma unroll
        for (int s = 0; s < 4; ++s) acc[r][s] = 0ull;

    for (int k = 0; k < P; ++k) {
        __syncthreads();

        // Stage W[k]: 2048 float4, 16 per thread, coalesced.
        const float4* Wk = (const float4*)(kw + (size_t)k * IN_F * OUT_F);
        float4*       Wv = (float4*)Ws;
#pragma unroll
        for (int j = 0; j < 16; ++j) Wv[tid + 128 * j] = Wk[tid + 128 * j];

        // Gather + scale + transpose A rows into As_t.
        {
            int   eidx = (c0 + frow) * P + k;
            int   src  = edge_src[eidx];
            float coef = g_coef[eidx];
            const float4* xr = (const float4*)(x + (size_t)src * IN_F);
#pragma unroll
            for (int j = 0; j < 4; ++j) {
                float4 v  = xr[fpart * 4 + j];
                int    i0 = fpart * 16 + j * 4;
                As_t[(i0 + 0) * AS_S + frow] = v.x * coef;
                As_t[(i0 + 1) * AS_S + frow] = v.y * coef;
                As_t[(i0 + 2) * AS_S + frow] = v.z * coef;
                As_t[(i0 + 3) * AS_S + frow] = v.w * coef;
            }
        }
        __syncthreads();

        // MAC: acc[r][*] += A[rt*4+r][i] * W[i][cols(cx)]
#pragma unroll 16
        for (int i = 0; i < IN_F; ++i) {
            float4 a4 = *(const float4*)(As_t + i * AS_S + rt * 4);
            const float* wrow = Ws + i * OUT_F;
            ulonglong2 w01 = *(const ulonglong2*)(wrow + cx * 4);
            ulonglong2 w23 = *(const ulonglong2*)(wrow + 64 + cx * 4);

            unsigned long long a0 = splat2(a4.x);
            unsigned long long a1 = splat2(a4.y);
            unsigned long long a2 = splat2(a4.z);
            unsigned long long a3 = splat2(a4.w);

            ffma2(acc[0][0], a0, w01.x); ffma2(acc[0][1], a0, w01.y);
            ffma2(acc[0][2], a0, w23.x); ffma2(acc[0][3], a0, w23.y);
            ffma2(acc[1][0], a1, w01.x); ffma2(acc[1][1], a1, w01.y);
            ffma2(acc[1][2], a1, w23.x); ffma2(acc[1][3], a1, w23.y);
            ffma2(acc[2][0], a2, w01.x); ffma2(acc[2][1], a2, w01.y);
            ffma2(acc[2][2], a2, w23.x); ffma2(acc[2][3], a2, w23.y);
            ffma2(acc[3][0], a3, w01.x); ffma2(acc[3][1], a3, w01.y);
            ffma2(acc[3][2], a3, w23.x); ffma2(acc[3][3], a3, w23.y);
        }
    }

    // Write [32,128] tile: per thread 4 rows x (two float4 col groups).
#pragma unroll
    for (int r = 0; r < 4; ++r) {
        int    c  = c0 + rt * 4 + r;
        float* op = out + (size_t)c * OUT_F;
        float2 p0 = *(float2*)&acc[r][0];
        float2 p1 = *(float2*)&acc[r][1];
        float2 p2 = *(float2*)&acc[r][2];
        float2 p3 = *(float2*)&acc[r][3];
        *(float4*)(op + cx * 4)      = make_float4(p0.x, p0.y, p1.x, p1.y);
        *(float4*)(op + 64 + cx * 4) = make_float4(p2.x, p2.y, p3.x, p3.y);
    }
}

extern "C" void kernel_launch(void* const* d_in, const int* in_sizes, int n_in,
                              void* d_out, int out_size)
{
    const float* x        = (const float*)d_in[0];
    const float* pos      = (const float*)d_in[1];
    const int*   edge_src = (const int*)  d_in[2];
    const int*   edge_tgt = (const int*)  d_in[3];
    const float* kpts     = (const float*)d_in[4];
    const float* kw       = (const float*)d_in[5];
    float*       out      = (float*)d_out;

    kp_geom_kernel<<<E / 256, 256>>>(pos, edge_src, edge_tgt, kpts);
    kp_main_kernel<<<NC / TM, 128>>>(x, edge_src, kw, out);
}

// round 3
// speedup vs baseline: 1.0857x; 1.0257x over previous
#include <cuda_runtime.h>

#define NPTS  32768
#define P     16
#define NC    8192
#define E     (NC * P)
#define IN_F  64
#define OUT_F 128
#define TMR   64                 // centers (rows) per CTA
#define KC    4                  // kernel points per CTA (k-split 4)
#define AS_S  68                 // As_t row stride (floats), mult of 4

// Scratch
__device__ float g_coef[E];                       // per-(center,k) coefficient
__device__ float g_part[3 * NC * OUT_F];          // k-split partial outputs

// ---------------------------------------------------------------------------
// Pass 1: geometry. One thread per edge; 16-lane shuffle-group reduction of
// (argmin kernel idx, clamped linear influence) into coef[c, 0..15].
// ---------------------------------------------------------------------------
__global__ void __launch_bounds__(256) kp_geom_kernel(
    const float* __restrict__ pos,
    const int*   __restrict__ edge_src,
    const int*   __restrict__ edge_tgt,
    const float* __restrict__ kpts)
{
    int e    = blockIdx.x * 256 + threadIdx.x;
    int lane = threadIdx.x & 31;

    int ti = edge_tgt[e];
    int si = edge_src[e];
    float rx = pos[ti * 3 + 0] - pos[si * 3 + 0];
    float ry = pos[ti * 3 + 1] - pos[si * 3 + 1];
    float rz = pos[ti * 3 + 2] - pos[si * 3 + 2];

    float best = 3.402823466e38f;
    int   nn   = 0;
#pragma unroll
    for (int k = 0; k < P; ++k) {
        float dx = rx - kpts[k * 3 + 0];
        float dy = ry - kpts[k * 3 + 1];
        float dz = rz - kpts[k * 3 + 2];
        float d2 = dx * dx + dy * dy + dz * dz;
        if (d2 < best) { best = d2; nn = k; }   // strict < == jnp.argmin first-min
    }
    float w = fmaxf(1.0f - sqrtf(best) * 1.5f, 0.0f);   // 1/KP_EXTENT = 1.5

    int   half = lane & 16;
    int   myk  = lane & 15;
    float coef = 0.0f;
#pragma unroll
    for (int j = 0; j < 16; ++j) {
        int   nnj = __shfl_sync(0xffffffffu, nn, half + j);
        float wj  = __shfl_sync(0xffffffffu, w,  half + j);
        if (nnj == myk) coef += wj;
    }
    g_coef[e] = coef;
}

// ---------------------------------------------------------------------------
// f32x2 helpers
// ---------------------------------------------------------------------------
__device__ __forceinline__ void ffma2(unsigned long long& d,
                                      unsigned long long a,
                                      unsigned long long b)
{
    asm("fma.rn.f32x2 %0, %1, %2, %0;" : "+l"(d) : "l"(a), "l"(b));
}
__device__ __forceinline__ unsigned long long splat2(float a)
{
    unsigned long long r;
    asm("mov.b64 %0, {%1, %1};" : "=l"(r) : "f"(a));
    return r;
}

// ---------------------------------------------------------------------------
// Pass 2: main compute. grid = (NC/TMR) * KSPLIT = 128 * 4 = 512 CTAs, 128 thr.
// CTA (tile, kc): centers [tile*64, tile*64+64), kernel points [kc*4, kc*4+4).
// Per k: stage W[k] (32KB) + gathered/scaled/transposed A (64x64) in smem,
// accumulate 8x8 register tiles with packed fma.rn.f32x2.
// kc==0 writes out directly; kc 1..3 write partial buffers.
// ---------------------------------------------------------------------------
__global__ void __launch_bounds__(128) kp_main_kernel(
    const float* __restrict__ x,
    const int*   __restrict__ edge_src,
    const float* __restrict__ kw,
    float*       __restrict__ out)
{
    __shared__ float Ws[IN_F * OUT_F];        // 32 KB, W[k] row-major [i][o]
    __shared__ float As_t[IN_F * AS_S];       // transposed A: As_t[i*AS_S + row]

    const int tid  = threadIdx.x;
    const int tile = blockIdx.x >> 2;
    const int kc   = blockIdx.x & 3;
    const int c0   = tile * TMR;
    const int k0   = kc * KC;

    // MAC mapping: cx in [0,16) -> cols {cx*4..+3, 64+cx*4..+3}
    //              rt in [0,8)  -> rows rt*8 .. rt*8+7
    const int cx = tid & 15;
    const int rt = tid >> 4;

    // Fill mapping: frow in [0,64) row, fpart in {0,1} -> i-range halves
    const int frow  = tid >> 1;
    const int fpart = tid & 1;

    unsigned long long acc[8][4];
#pragma unroll
    for (int r = 0; r < 8; ++r)
#pragma unroll
        for (int s = 0; s < 4; ++s) acc[r][s] = 0ull;

    for (int kk = 0; kk < KC; ++kk) {
        const int k = k0 + kk;
        __syncthreads();

        // Stage W[k]: 2048 float4, 16 per thread, coalesced.
        const float4* Wk = (const float4*)(kw + (size_t)k * IN_F * OUT_F);
        float4*       Wv = (float4*)Ws;
#pragma unroll
        for (int j = 0; j < 16; ++j) Wv[tid + 128 * j] = Wk[tid + 128 * j];

        // Gather + scale + transpose A rows into As_t (2 threads per row).
        {
            int   eidx = (c0 + frow) * P + k;
            int   src  = edge_src[eidx];
            float coef = g_coef[eidx];
            const float4* xr = (const float4*)(x + (size_t)src * IN_F) + fpart * 8;
#pragma unroll
            for (int j = 0; j < 8; ++j) {
                float4 v  = xr[j];
                int    i0 = fpart * 32 + j * 4;
                As_t[(i0 + 0) * AS_S + frow] = v.x * coef;
                As_t[(i0 + 1) * AS_S + frow] = v.y * coef;
                As_t[(i0 + 2) * AS_S + frow] = v.z * coef;
                As_t[(i0 + 3) * AS_S + frow] = v.w * coef;
            }
        }
        __syncthreads();

        // MAC: acc[r][*] += A[rt*8+r][i] * W[i][cols(cx)]
#pragma unroll 8
        for (int i = 0; i < IN_F; ++i) {
            const float* at = As_t + i * AS_S + rt * 8;
            float4 aA = *(const float4*)(at);
            float4 aB = *(const float4*)(at + 4);
            const float* wrow = Ws + i * OUT_F;
            ulonglong2 w01 = *(const ulonglong2*)(wrow + cx * 4);
            ulonglong2 w23 = *(const ulonglong2*)(wrow + 64 + cx * 4);

            unsigned long long a0 = splat2(aA.x), a1 = splat2(aA.y);
            unsigned long long a2 = splat2(aA.z), a3 = splat2(aA.w);
            unsigned long long a4 = splat2(aB.x), a5 = splat2(aB.y);
            unsigned long long a6 = splat2(aB.z), a7 = splat2(aB.w);

            ffma2(acc[0][0], a0, w01.x); ffma2(acc[0][1], a0, w01.y);
            ffma2(acc[0][2], a0, w23.x); ffma2(acc[0][3], a0, w23.y);
            ffma2(acc[1][0], a1, w01.x); ffma2(acc[1][1], a1, w01.y);
            ffma2(acc[1][2], a1, w23.x); ffma2(acc[1][3], a1, w23.y);
            ffma2(acc[2][0], a2, w01.x); ffma2(acc[2][1], a2, w01.y);
            ffma2(acc[2][2], a2, w23.x); ffma2(acc[2][3], a2, w23.y);
            ffma2(acc[3][0], a3, w01.x); ffma2(acc[3][1], a3, w01.y);
            ffma2(acc[3][2], a3, w23.x); ffma2(acc[3][3], a3, w23.y);
            ffma2(acc[4][0], a4, w01.x); ffma2(acc[4][1], a4, w01.y);
            ffma2(acc[4][2], a4, w23.x); ffma2(acc[4][3], a4, w23.y);
            ffma2(acc[5][0], a5, w01.x); ffma2(acc[5][1], a5, w01.y);
            ffma2(acc[5][2], a5, w23.x); ffma2(acc[5][3], a5, w23.y);
            ffma2(acc[6][0], a6, w01.x); ffma2(acc[6][1], a6, w01.y);
            ffma2(acc[6][2], a6, w23.x); ffma2(acc[6][3], a6, w23.y);
            ffma2(acc[7][0], a7, w01.x); ffma2(acc[7][1], a7, w01.y);
            ffma2(acc[7][2], a7, w23.x); ffma2(acc[7][3], a7, w23.y);
        }
    }

    // Write [64,128] tile: kc==0 -> out, else partial buffer kc-1.
    float* dst = (kc == 0) ? out : (g_part + (size_t)(kc - 1) * NC * OUT_F);
#pragma unroll
    for (int r = 0; r < 8; ++r) {
        int    c  = c0 + rt * 8 + r;
        float* op = dst + (size_t)c * OUT_F;
        float2 p0 = *(float2*)&acc[r][0];
        float2 p1 = *(float2*)&acc[r][1];
        float2 p2 = *(float2*)&acc[r][2];
        float2 p3 = *(float2*)&acc[r][3];
        *(float4*)(op + cx * 4)      = make_float4(p0.x, p0.y, p1.x, p1.y);
        *(float4*)(op + 64 + cx * 4) = make_float4(p2.x, p2.y, p3.x, p3.y);
    }
}

// ---------------------------------------------------------------------------
// Pass 3: fold k-split partials into out. 262144 float4 elements.
// ---------------------------------------------------------------------------
__global__ void __launch_bounds__(256) kp_reduce_kernel(float* __restrict__ out)
{
    int idx = blockIdx.x * 256 + threadIdx.x;
    const float4* p0 = (const float4*)(g_part);
    const float4* p1 = (const float4*)(g_part + (size_t)NC * OUT_F);
    const float4* p2 = (const float4*)(g_part + (size_t)2 * NC * OUT_F);
    float4* o = (float4*)out;

    float4 v = o[idx];
    float4 a = p0[idx];
    float4 b = p1[idx];
    float4 c = p2[idx];
    v.x += a.x + b.x + c.x;
    v.y += a.y + b.y + c.y;
    v.z += a.z + b.z + c.z;
    v.w += a.w + b.w + c.w;
    o[idx] = v;
}

extern "C" void kernel_launch(void* const* d_in, const int* in_sizes, int n_in,
                              void* d_out, int out_size)
{
    const float* x        = (const float*)d_in[0];
    const float* pos      = (const float*)d_in[1];
    const int*   edge_src = (const int*)  d_in[2];
    const int*   edge_tgt = (const int*)  d_in[3];
    const float* kpts     = (const float*)d_in[4];
    const float* kw       = (const float*)d_in[5];
    float*       out      = (float*)d_out;

    kp_geom_kernel<<<E / 256, 256>>>(pos, edge_src, edge_tgt, kpts);
    kp_main_kernel<<<(NC / TMR) * (P / KC), 128>>>(x, edge_src, kw, out);
    kp_reduce_kernel<<<NC * OUT_F / 4 / 256, 256>>>(out);
}

// round 5
// speedup vs baseline: 1.7784x; 1.6380x over previous
#include <cuda_runtime.h>
#include <cuda_bf16.h>
#include <cstdint>

#define NPTS  32768
#define P     16
#define NC    8192
#define E     (NC * P)
#define IN_F  64
#define OUT_F 128
#define TMR   64                  // centers per CTA

// smem stage layout (bytes): Ah | Al | Wh | Wl, rows padded to 144B
#define LDA    144u
#define AH_OFF 0u
#define AL_OFF 9216u
#define WH_OFF 18432u
#define WL_OFF 36864u
#define STAGE  55296u
#define SMEM_DYN (2 * 55296)

// Scratch
__device__ float    g_coef[E];
__device__ uint32_t g_wimg[P * 2 * 4096];  // per k: hi[128][32w] then lo[128][32w] (Wt[n][i] bf16)

// ---------------------------------------------------------------------------
// helpers
// ---------------------------------------------------------------------------
__device__ __forceinline__ uint32_t smem_u32(const void* p) {
    uint32_t a;
    asm("{ .reg .u64 t; cvta.to.shared.u64 t, %1; cvt.u32.u64 %0, t; }"
        : "=r"(a) : "l"(p));
    return a;
}
__device__ __forceinline__ uint32_t pack_hi(float a, float b, float& ra, float& rb) {
    __nv_bfloat16 ha = __float2bfloat16(a);
    __nv_bfloat16 hb = __float2bfloat16(b);
    ra = a - __bfloat162float(ha);
    rb = b - __bfloat162float(hb);
    return (uint32_t)__bfloat16_as_ushort(ha) | ((uint32_t)__bfloat16_as_ushort(hb) << 16);
}
__device__ __forceinline__ uint32_t pack2(float a, float b) {
    uint32_t r;
    asm("cvt.rn.bf16x2.f32 %0, %1, %2;" : "=r"(r) : "f"(b), "f"(a));
    return r;
}
__device__ __forceinline__ void cp_async16(uint32_t dst, const void* g) {
    asm volatile("cp.async.cg.shared.global [%0], [%1], 16;" :: "r"(dst), "l"(g));
}

#define LDSM4(r, addr) asm volatile( \
    "ldmatrix.sync.aligned.m8n8.x4.shared.b16 {%0,%1,%2,%3}, [%4];" \
    : "=r"((r)[0]), "=r"((r)[1]), "=r"((r)[2]), "=r"((r)[3]) : "r"(addr))
#define LDSM2(r, addr) asm volatile( \
    "ldmatrix.sync.aligned.m8n8.x2.shared.b16 {%0,%1}, [%2];" \
    : "=r"((r)[0]), "=r"((r)[1]) : "r"(addr))
#define MMA(d, a, b) asm volatile( \
    "mma.sync.aligned.m16n8k16.row.col.f32.bf16.bf16.f32 " \
    "{%0,%1,%2,%3},{%4,%5,%6,%7},{%8,%9},{%0,%1,%2,%3};" \
    : "+f"((d)[0]), "+f"((d)[1]), "+f"((d)[2]), "+f"((d)[3]) \
    : "r"((a)[0]), "r"((a)[1]), "r"((a)[2]), "r"((a)[3]), "r"((b)[0]), "r"((b)[1]))

// ---------------------------------------------------------------------------
// Pass 1 (fused): blocks [0,512) geometry coefficients; blocks [512,768) build
// bf16 hi/lo transposed W images Wt[n][i].
// ---------------------------------------------------------------------------
__global__ void __launch_bounds__(256) kp_prep_kernel(
    const float* __restrict__ pos,
    const int*   __restrict__ edge_src,
    const int*   __restrict__ edge_tgt,
    const float* __restrict__ kpts,
    const float* __restrict__ kw)
{
    if (blockIdx.x < 512) {
        int e    = blockIdx.x * 256 + threadIdx.x;
        int lane = threadIdx.x & 31;

        int ti = edge_tgt[e];
        int si = edge_src[e];
        float rx = pos[ti * 3 + 0] - pos[si * 3 + 0];
        float ry = pos[ti * 3 + 1] - pos[si * 3 + 1];
        float rz = pos[ti * 3 + 2] - pos[si * 3 + 2];

        float best = 3.402823466e38f;
        int   nn   = 0;
#pragma unroll
        for (int k = 0; k < P; ++k) {
            float dx = rx - kpts[k * 3 + 0];
            float dy = ry - kpts[k * 3 + 1];
            float dz = rz - kpts[k * 3 + 2];
            float d2 = dx * dx + dy * dy + dz * dz;
            if (d2 < best) { best = d2; nn = k; }   // strict < == jnp.argmin
        }
        float w = fmaxf(1.0f - sqrtf(best) * 1.5f, 0.0f);   // 1/KP_EXTENT = 1.5

        int   half = lane & 16;
        int   myk  = lane & 15;
        float coef = 0.0f;
#pragma unroll
        for (int j = 0; j < 16; ++j) {
            int   nnj = __shfl_sync(0xffffffffu, nn, half + j);
            float wj  = __shfl_sync(0xffffffffu, w,  half + j);
            if (nnj == myk) coef += wj;
        }
        g_coef[e] = coef;
    } else {
        // Wt[n][i] bf16 hi/lo: word (k, n, i2) holds elems i=2*i2, 2*i2+1.
        int t  = (blockIdx.x - 512) * 256 + threadIdx.x;    // [0, 65536)
        int n  = t & 127;
        int i2 = (t >> 7) & 31;
        int k  = t >> 12;
        const float* wp = kw + ((size_t)k * IN_F + 2 * i2) * OUT_F + n;
        float w0 = wp[0], w1 = wp[OUT_F];
        float r0, r1;
        uint32_t hi = pack_hi(w0, w1, r0, r1);
        uint32_t lo = pack2(r0, r1);
        g_wimg[(k * 2 + 0) * 4096 + n * 32 + i2] = hi;
        g_wimg[(k * 2 + 1) * 4096 + n * 32 + i2] = lo;
    }
}

// ---------------------------------------------------------------------------
// Pass 2: mma.sync bf16 3-pass. 128 CTAs x 256 thr. CTA: 64 centers x 128 cols,
// all 16 kernel points accumulated in registers.
// ---------------------------------------------------------------------------
__global__ void __launch_bounds__(256, 1) kp_mma_kernel(
    const float* __restrict__ x,
    const int*   __restrict__ edge_src,
    float*       __restrict__ out)
{
    extern __shared__ __align__(128) char smem[];
    const uint32_t sb   = smem_u32(smem);
    const int      tid  = threadIdx.x;
    const int      lane = tid & 31;
    const int      w    = tid >> 5;
    const int      wm   = w >> 2;          // 2 row halves (32 rows each)
    const int      wn   = w & 3;           // 4 col quarters (32 cols each)
    const int      c0   = blockIdx.x * TMR;

    // A-build mapping: thread -> row ar, 16-col part ap
    const int ar = tid >> 2;
    const int ap = tid & 3;

    // All 16 (src, coef) for this thread's row: contiguous 64B each.
    int   src[16];
    float cf[16];
    {
        const int4*   sp = (const int4*)(edge_src + (size_t)(c0 + ar) * P);
        const float4* cp = (const float4*)(g_coef + (size_t)(c0 + ar) * P);
#pragma unroll
        for (int q = 0; q < 4; ++q) {
            int4   s4 = sp[q];
            float4 c4 = cp[q];
            src[4*q+0] = s4.x; src[4*q+1] = s4.y; src[4*q+2] = s4.z; src[4*q+3] = s4.w;
            cf[4*q+0]  = c4.x; cf[4*q+1]  = c4.y; cf[4*q+2]  = c4.z; cf[4*q+3]  = c4.w;
        }
    }

    float acc[2][4][4];
#pragma unroll
    for (int mt = 0; mt < 2; ++mt)
#pragma unroll
        for (int nt = 0; nt < 4; ++nt)
#pragma unroll
            for (int q = 0; q < 4; ++q) acc[mt][nt][q] = 0.0f;

    // Prologue: x rows for k=0 into regs; W[0] cp.async into stage 0.
    float4 xv[4];
    {
        const float4* xr = (const float4*)(x + (size_t)src[0] * IN_F) + ap * 4;
#pragma unroll
        for (int q = 0; q < 4; ++q) xv[q] = xr[q];
    }
#pragma unroll
    for (int hl = 0; hl < 2; ++hl) {
        uint32_t    wd = sb + (hl ? WL_OFF : WH_OFF);
        const char* ws = (const char*)(g_wimg + (0 * 2 + hl) * 4096);
#pragma unroll
        for (int jj = 0; jj < 4; ++jj) {
            int j = tid + 256 * jj;
            cp_async16(wd + (uint32_t)(j >> 3) * LDA + (uint32_t)(j & 7) * 16, ws + (size_t)j * 16);
        }
    }
    asm volatile("cp.async.commit_group;" ::: "memory");

#pragma unroll 1
    for (int k = 0; k < P; ++k) {
        const uint32_t s  = (uint32_t)(k & 1) * STAGE;
        const uint32_t ns = s ^ STAGE;

        // Pack + STS A[k] (from xv) into stage s.
        {
            float c = cf[k];
            float a0 = xv[0].x * c, a1 = xv[0].y * c, a2 = xv[0].z * c, a3 = xv[0].w * c;
            float a4 = xv[1].x * c, a5 = xv[1].y * c, a6 = xv[1].z * c, a7 = xv[1].w * c;
            float b0 = xv[2].x * c, b1 = xv[2].y * c, b2 = xv[2].z * c, b3 = xv[2].w * c;
            float b4 = xv[3].x * c, b5 = xv[3].y * c, b6 = xv[3].z * c, b7 = xv[3].w * c;
            float r0, r1, r2, r3, r4, r5, r6, r7;
            float t0, t1, t2, t3, t4, t5, t6, t7;
            uint4 h0, h1, l0, l1;
            h0.x = pack_hi(a0, a1, r0, r1); h0.y = pack_hi(a2, a3, r2, r3);
            h0.z = pack_hi(a4, a5, r4, r5); h0.w = pack_hi(a6, a7, r6, r7);
            h1.x = pack_hi(b0, b1, t0, t1); h1.y = pack_hi(b2, b3, t2, t3);
            h1.z = pack_hi(b4, b5, t4, t5); h1.w = pack_hi(b6, b7, t6, t7);
            l0.x = pack2(r0, r1); l0.y = pack2(r2, r3);
            l0.z = pack2(r4, r5); l0.w = pack2(r6, r7);
            l1.x = pack2(t0, t1); l1.y = pack2(t2, t3);
            l1.z = pack2(t4, t5); l1.w = pack2(t6, t7);
            char* pa = smem + s + AH_OFF + (uint32_t)ar * LDA + (uint32_t)ap * 32;
            char* pl = smem + s + AL_OFF + (uint32_t)ar * LDA + (uint32_t)ap * 32;
            *(uint4*)(pa)      = h0;
            *(uint4*)(pa + 16) = h1;
            *(uint4*)(pl)      = l0;
            *(uint4*)(pl + 16) = l1;
        }

        if (k < P - 1) {
            // Prefetch x rows for k+1.
            const float4* xr = (const float4*)(x + (size_t)src[k + 1] * IN_F) + ap * 4;
#pragma unroll
            for (int q = 0; q < 4; ++q) xv[q] = xr[q];
            // cp.async W[k+1] into stage ns.
#pragma unroll
            for (int hl = 0; hl < 2; ++hl) {
                uint32_t    wd = sb + ns + (hl ? WL_OFF : WH_OFF);
                const char* ws = (const char*)(g_wimg + ((k + 1) * 2 + hl) * 4096);
#pragma unroll
                for (int jj = 0; jj < 4; ++jj) {
                    int j = tid + 256 * jj;
                    cp_async16(wd + (uint32_t)(j >> 3) * LDA + (uint32_t)(j & 7) * 16,
                               ws + (size_t)j * 16);
                }
            }
            asm volatile("cp.async.commit_group;" ::: "memory");
            asm volatile("cp.async.wait_group 1;" ::: "memory");
        } else {
            asm volatile("cp.async.wait_group 0;" ::: "memory");
        }
        __syncthreads();

        // MMA over stage s: 4 ksteps of 16.
        const uint32_t aBase = sb + s + AH_OFF +
            (uint32_t)(wm * 32 + (lane & 15)) * LDA + (uint32_t)(lane >> 4) * 16;
        const uint32_t bBase = sb + s + WH_OFF +
            (uint32_t)(wn * 32 + (lane & 7)) * LDA + (uint32_t)((lane >> 3) & 1) * 16;
#pragma unroll
        for (int ks = 0; ks < 4; ++ks) {
            uint32_t ah[2][4], al[2][4], bh[4][2], bl[4][2];
            uint32_t ao = aBase + (uint32_t)ks * 32;
            uint32_t bo = bBase + (uint32_t)ks * 32;
            LDSM4(ah[0], ao);
            LDSM4(ah[1], ao + 16 * LDA);
            LDSM4(al[0], ao + (AL_OFF - AH_OFF));
            LDSM4(al[1], ao + (AL_OFF - AH_OFF) + 16 * LDA);
#pragma unroll
            for (int nt = 0; nt < 4; ++nt) {
                LDSM2(bh[nt], bo + (uint32_t)nt * 8 * LDA);
                LDSM2(bl[nt], bo + (uint32_t)nt * 8 * LDA + (WL_OFF - WH_OFF));
            }
#pragma unroll
            for (int mt = 0; mt < 2; ++mt)
#pragma unroll
                for (int nt = 0; nt < 4; ++nt) {
                    MMA(acc[mt][nt], ah[mt], bh[nt]);
                    MMA(acc[mt][nt], ah[mt], bl[nt]);
                    MMA(acc[mt][nt], al[mt], bh[nt]);
                }
        }
        __syncthreads();
    }

    // Epilogue: write [64,128] tile.
#pragma unroll
    for (int mt = 0; mt < 2; ++mt)
#pragma unroll
        for (int nt = 0; nt < 4; ++nt) {
            int    row = c0 + wm * 32 + mt * 16 + (lane >> 2);
            int    col = wn * 32 + nt * 8 + (lane & 3) * 2;
            float* o   = out + (size_t)row * OUT_F + col;
            *(float2*)o                 = make_float2(acc[mt][nt][0], acc[mt][nt][1]);
            *(float2*)(o + 8 * OUT_F)   = make_float2(acc[mt][nt][2], acc[mt][nt][3]);
        }
}

extern "C" void kernel_launch(void* const* d_in, const int* in_sizes, int n_in,
                              void* d_out, int out_size)
{
    const float* x        = (const float*)d_in[0];
    const float* pos      = (const float*)d_in[1];
    const int*   edge_src = (const int*)  d_in[2];
    const int*   edge_tgt = (const int*)  d_in[3];
    const float* kpts     = (const float*)d_in[4];
    const float* kw       = (const float*)d_in[5];
    float*       out      = (float*)d_out;

    cudaFuncSetAttribute(kp_mma_kernel,
                         cudaFuncAttributeMaxDynamicSharedMemorySize, SMEM_DYN);

    kp_prep_kernel<<<768, 256>>>(pos, edge_src, edge_tgt, kpts, kw);
    kp_mma_kernel<<<NC / TMR, 256, SMEM_DYN>>>(x, edge_src, out);
}

// round 6
// speedup vs baseline: 1.9277x; 1.0840x over previous
#include <cuda_runtime.h>
#include <cuda_bf16.h>
#include <cstdint>

#define NPTS  32768
#define P     16
#define NC    8192
#define E     (NC * P)
#define IN_F  64
#define OUT_F 128
#define TMR   32                  // centers per CTA

// smem stage layout (bytes): Ah | Al | Wh | Wl, rows padded to 144B
#define LDA    144u
#define AH_OFF 0u
#define AL_OFF 4608u
#define WH_OFF 9216u
#define WL_OFF 27648u
#define STAGE  46080u
#define SMEM_DYN (2 * 46080)

// Scratch
__device__ float    g_coef[E];
__device__ uint32_t g_wimg[P * 2 * 4096];  // per k: hi[128][32w] then lo[128][32w] (Wt[n][i] bf16)

// ---------------------------------------------------------------------------
// helpers
// ---------------------------------------------------------------------------
__device__ __forceinline__ uint32_t smem_u32(const void* p) {
    uint32_t a;
    asm("{ .reg .u64 t; cvta.to.shared.u64 t, %1; cvt.u32.u64 %0, t; }"
        : "=r"(a) : "l"(p));
    return a;
}
__device__ __forceinline__ uint32_t pack_hi(float a, float b, float& ra, float& rb) {
    __nv_bfloat16 ha = __float2bfloat16(a);
    __nv_bfloat16 hb = __float2bfloat16(b);
    ra = a - __bfloat162float(ha);
    rb = b - __bfloat162float(hb);
    return (uint32_t)__bfloat16_as_ushort(ha) | ((uint32_t)__bfloat16_as_ushort(hb) << 16);
}
__device__ __forceinline__ uint32_t pack2(float a, float b) {
    uint32_t r;
    asm("cvt.rn.bf16x2.f32 %0, %1, %2;" : "=r"(r) : "f"(b), "f"(a));
    return r;
}
__device__ __forceinline__ void cp_async16(uint32_t dst, const void* g) {
    asm volatile("cp.async.cg.shared.global [%0], [%1], 16;" :: "r"(dst), "l"(g));
}

#define LDSM4(r, addr) asm volatile( \
    "ldmatrix.sync.aligned.m8n8.x4.shared.b16 {%0,%1,%2,%3}, [%4];" \
    : "=r"((r)[0]), "=r"((r)[1]), "=r"((r)[2]), "=r"((r)[3]) : "r"(addr))
#define MMA(d, a, b0, b1) asm volatile( \
    "mma.sync.aligned.m16n8k16.row.col.f32.bf16.bf16.f32 " \
    "{%0,%1,%2,%3},{%4,%5,%6,%7},{%8,%9},{%0,%1,%2,%3};" \
    : "+f"((d)[0]), "+f"((d)[1]), "+f"((d)[2]), "+f"((d)[3]) \
    : "r"((a)[0]), "r"((a)[1]), "r"((a)[2]), "r"((a)[3]), "r"(b0), "r"(b1))

// ---------------------------------------------------------------------------
// Pass 1 (fused): blocks [0,512) geometry coefficients; blocks [512,768) build
// bf16 hi/lo transposed W images Wt[n][i].
// ---------------------------------------------------------------------------
__global__ void __launch_bounds__(256) kp_prep_kernel(
    const float* __restrict__ pos,
    const int*   __restrict__ edge_src,
    const int*   __restrict__ edge_tgt,
    const float* __restrict__ kpts,
    const float* __restrict__ kw)
{
    if (blockIdx.x < 512) {
        int e    = blockIdx.x * 256 + threadIdx.x;
        int lane = threadIdx.x & 31;

        int ti = edge_tgt[e];
        int si = edge_src[e];
        float rx = pos[ti * 3 + 0] - pos[si * 3 + 0];
        float ry = pos[ti * 3 + 1] - pos[si * 3 + 1];
        float rz = pos[ti * 3 + 2] - pos[si * 3 + 2];

        float best = 3.402823466e38f;
        int   nn   = 0;
#pragma unroll
        for (int k = 0; k < P; ++k) {
            float dx = rx - kpts[k * 3 + 0];
            float dy = ry - kpts[k * 3 + 1];
            float dz = rz - kpts[k * 3 + 2];
            float d2 = dx * dx + dy * dy + dz * dz;
            if (d2 < best) { best = d2; nn = k; }   // strict < == jnp.argmin
        }
        float w = fmaxf(1.0f - sqrtf(best) * 1.5f, 0.0f);   // 1/KP_EXTENT = 1.5

        int   half = lane & 16;
        int   myk  = lane & 15;
        float coef = 0.0f;
#pragma unroll
        for (int j = 0; j < 16; ++j) {
            int   nnj = __shfl_sync(0xffffffffu, nn, half + j);
            float wj  = __shfl_sync(0xffffffffu, w,  half + j);
            if (nnj == myk) coef += wj;
        }
        g_coef[e] = coef;
    } else {
        // Wt[n][i] bf16 hi/lo: word (k, n, i2) holds elems i=2*i2, 2*i2+1.
        int t  = (blockIdx.x - 512) * 256 + threadIdx.x;    // [0, 65536)
        int n  = t & 127;
        int i2 = (t >> 7) & 31;
        int k  = t >> 12;
        const float* wp = kw + ((size_t)k * IN_F + 2 * i2) * OUT_F + n;
        float w0 = wp[0], w1 = wp[OUT_F];
        float r0, r1;
        uint32_t hi = pack_hi(w0, w1, r0, r1);
        uint32_t lo = pack2(r0, r1);
        g_wimg[(k * 2 + 0) * 4096 + n * 32 + i2] = hi;
        g_wimg[(k * 2 + 1) * 4096 + n * 32 + i2] = lo;
    }
}

// ---------------------------------------------------------------------------
// Pass 2: mma.sync bf16 3-pass. 256 CTAs x 256 thr (2 CTAs/SM).
// CTA: 32 centers x 128 cols, all 16 kernel points accumulated in registers.
// Warp w covers cols [w*16, w*16+16), all 32 rows.
// ---------------------------------------------------------------------------
__global__ void __launch_bounds__(256, 2) kp_mma_kernel(
    const float* __restrict__ x,
    const int*   __restrict__ edge_src,
    float*       __restrict__ out)
{
    extern __shared__ __align__(128) char smem[];
    const uint32_t sb   = smem_u32(smem);
    const int      tid  = threadIdx.x;
    const int      lane = tid & 31;
    const int      w    = tid >> 5;
    const int      c0   = blockIdx.x * TMR;

    // A-build mapping: 8 threads per row; thread covers 8 floats (16B bf16x8)
    const int ar = tid >> 3;          // row 0..31
    const int ap = tid & 7;           // col part: floats [ap*8, ap*8+8)

    float acc[2][2][4];
#pragma unroll
    for (int mt = 0; mt < 2; ++mt)
#pragma unroll
        for (int nt = 0; nt < 2; ++nt)
#pragma unroll
            for (int q = 0; q < 4; ++q) acc[mt][nt][q] = 0.0f;

    // Rolling per-k scalars: (src, coef) and the x row slice in registers.
    const int* srow = edge_src + (size_t)(c0 + ar) * P;
    const float* crow = g_coef + (size_t)(c0 + ar) * P;

    int   src_c = srow[0];
    float cf_c  = crow[0];
    float4 xv[2];
    {
        const float4* xr = (const float4*)(x + (size_t)src_c * IN_F) + ap * 2;
        xv[0] = xr[0]; xv[1] = xr[1];
    }
    // W[0] cp.async into stage 0: 2 halves x 1024 16B-chunks.
#pragma unroll
    for (int hl = 0; hl < 2; ++hl) {
        uint32_t    wd = sb + (hl ? WL_OFF : WH_OFF);
        const char* ws = (const char*)(g_wimg + (0 * 2 + hl) * 4096);
#pragma unroll
        for (int jj = 0; jj < 4; ++jj) {
            int j = tid + 256 * jj;
            cp_async16(wd + (uint32_t)(j >> 3) * LDA + (uint32_t)(j & 7) * 16,
                       ws + (size_t)j * 16);
        }
    }
    asm volatile("cp.async.commit_group;" ::: "memory");

#pragma unroll 1
    for (int k = 0; k < P; ++k) {
        const uint32_t s  = (uint32_t)(k & 1) * STAGE;
        const uint32_t ns = s ^ STAGE;

        // Pack + STS A[k] from (xv, cf_c).
        {
            float c = cf_c;
            float a0 = xv[0].x * c, a1 = xv[0].y * c, a2 = xv[0].z * c, a3 = xv[0].w * c;
            float a4 = xv[1].x * c, a5 = xv[1].y * c, a6 = xv[1].z * c, a7 = xv[1].w * c;
            float r0, r1, r2, r3, r4, r5, r6, r7;
            uint4 h, l;
            h.x = pack_hi(a0, a1, r0, r1); h.y = pack_hi(a2, a3, r2, r3);
            h.z = pack_hi(a4, a5, r4, r5); h.w = pack_hi(a6, a7, r6, r7);
            l.x = pack2(r0, r1); l.y = pack2(r2, r3);
            l.z = pack2(r4, r5); l.w = pack2(r6, r7);
            uint32_t off = (uint32_t)ar * LDA + (uint32_t)ap * 16;
            *(uint4*)(smem + s + AH_OFF + off) = h;
            *(uint4*)(smem + s + AL_OFF + off) = l;
        }

        if (k < P - 1) {
            // Rolling prefetch for k+1: (src, coef) then the x row slice.
            src_c = srow[k + 1];
            cf_c  = crow[k + 1];
            const float4* xr = (const float4*)(x + (size_t)src_c * IN_F) + ap * 2;
            xv[0] = xr[0]; xv[1] = xr[1];
            // cp.async W[k+1] into stage ns.
#pragma unroll
            for (int hl = 0; hl < 2; ++hl) {
                uint32_t    wd = sb + ns + (hl ? WL_OFF : WH_OFF);
                const char* ws = (const char*)(g_wimg + ((k + 1) * 2 + hl) * 4096);
#pragma unroll
                for (int jj = 0; jj < 4; ++jj) {
                    int j = tid + 256 * jj;
                    cp_async16(wd + (uint32_t)(j >> 3) * LDA + (uint32_t)(j & 7) * 16,
                               ws + (size_t)j * 16);
                }
            }
            asm volatile("cp.async.commit_group;" ::: "memory");
            asm volatile("cp.async.wait_group 1;" ::: "memory");
        } else {
            asm volatile("cp.async.wait_group 0;" ::: "memory");
        }
        __syncthreads();

        // MMA over stage s: 4 ksteps of 16.
        // A frag x4 addr: rows (lane&15), +16B for k-hi half (lane>>4).
        const uint32_t aBase = sb + s + AH_OFF +
            (uint32_t)(lane & 15) * LDA + (uint32_t)(lane >> 4) * 16;
        // B frag x4 addr: rows w*16 + (lane>>4)*8 + (lane&7)  (2 n-tiles),
        // +16B for k-hi half ((lane>>3)&1).
        const uint32_t bBase = sb + s + WH_OFF +
            (uint32_t)(w * 16 + ((lane >> 4) << 3) + (lane & 7)) * LDA +
            (uint32_t)((lane >> 3) & 1) * 16;
#pragma unroll
        for (int ks = 0; ks < 4; ++ks) {
            uint32_t ah[2][4], al[2][4], bh[4], bl[4];
            uint32_t ao = aBase + (uint32_t)ks * 32;
            uint32_t bo = bBase + (uint32_t)ks * 32;
            LDSM4(ah[0], ao);
            LDSM4(ah[1], ao + 16 * LDA);
            LDSM4(al[0], ao + (AL_OFF - AH_OFF));
            LDSM4(al[1], ao + (AL_OFF - AH_OFF) + 16 * LDA);
            LDSM4(bh, bo);
            LDSM4(bl, bo + (WL_OFF - WH_OFF));

            // Pass-outer order: 4 independent accumulators between reuses.
#pragma unroll
            for (int mt = 0; mt < 2; ++mt)
#pragma unroll
                for (int nt = 0; nt < 2; ++nt)
                    MMA(acc[mt][nt], ah[mt], bh[2 * nt], bh[2 * nt + 1]);
#pragma unroll
            for (int mt = 0; mt < 2; ++mt)
#pragma unroll
                for (int nt = 0; nt < 2; ++nt)
                    MMA(acc[mt][nt], ah[mt], bl[2 * nt], bl[2 * nt + 1]);
#pragma unroll
            for (int mt = 0; mt < 2; ++mt)
#pragma unroll
                for (int nt = 0; nt < 2; ++nt)
                    MMA(acc[mt][nt], al[mt], bh[2 * nt], bh[2 * nt + 1]);
        }
        __syncthreads();
    }

    // Epilogue: write [32,128] tile.
#pragma unroll
    for (int mt = 0; mt < 2; ++mt)
#pragma unroll
        for (int nt = 0; nt < 2; ++nt) {
            int    row = c0 + mt * 16 + (lane >> 2);
            int    col = w * 16 + nt * 8 + (lane & 3) * 2;
            float* o   = out + (size_t)row * OUT_F + col;
            *(float2*)o               = make_float2(acc[mt][nt][0], acc[mt][nt][1]);
            *(float2*)(o + 8 * OUT_F) = make_float2(acc[mt][nt][2], acc[mt][nt][3]);
        }
}

extern "C" void kernel_launch(void* const* d_in, const int* in_sizes, int n_in,
                              void* d_out, int out_size)
{
    const float* x        = (const float*)d_in[0];
    const float* pos      = (const float*)d_in[1];
    const int*   edge_src = (const int*)  d_in[2];
    const int*   edge_tgt = (const int*)  d_in[3];
    const float* kpts     = (const float*)d_in[4];
    const float* kw       = (const float*)d_in[5];
    float*       out      = (float*)d_out;

    cudaFuncSetAttribute(kp_mma_kernel,
                         cudaFuncAttributeMaxDynamicSharedMemorySize, SMEM_DYN);

    kp_prep_kernel<<<768, 256>>>(pos, edge_src, edge_tgt, kpts, kw);
    kp_mma_kernel<<<NC / TMR, 256, SMEM_DYN>>>(x, edge_src, out);
}